// round 10
// baseline (speedup 1.0000x reference)
#include <cuda_runtime.h>
#include <cuda_fp16.h>
#include <math.h>

#define E_NUM   600000
#define NRAD    6
#define HID     128
#define NNODES  50000
#define NT      782          // 64-node tiles

// hacc: zero at module load (BSS); re-zeroed by mlp_kernel after consumption,
// so it is 0 at the start of every kernel_launch call (graph-replay invariant).
__device__ float g_hacc[(size_t)NNODES * HID];
__device__ __align__(256) __half g_wimg[14 * 16384];   // 14 chunk-tiles x 32KB (fp16, swizzled, W^T)

// ---------------- helpers ----------------
__device__ __forceinline__ void cpa16(void* dst, const void* src) {
    unsigned d = (unsigned)__cvta_generic_to_shared(dst);
    asm volatile("cp.async.cg.shared.global [%0], [%1], 16;" :: "r"(d), "l"(src));
}
#define CP_COMMIT() asm volatile("cp.async.commit_group;" ::: "memory")
#define CP_WAIT1()  asm volatile("cp.async.wait_group 1;" ::: "memory")
#define CP_WAIT0()  asm volatile("cp.async.wait_group 0;" ::: "memory")

__device__ __forceinline__ void mma16816(float* c, const unsigned* a, unsigned b0, unsigned b1) {
    asm volatile("mma.sync.aligned.m16n8k16.row.col.f32.f16.f16.f32 "
                 "{%0,%1,%2,%3}, {%4,%5,%6,%7}, {%8,%9}, {%0,%1,%2,%3};"
                 : "+f"(c[0]), "+f"(c[1]), "+f"(c[2]), "+f"(c[3])
                 : "r"(a[0]), "r"(a[1]), "r"(a[2]), "r"(a[3]), "r"(b0), "r"(b1));
}
__device__ __forceinline__ unsigned packh2(float x, float y) {
    __half2 h = __floats2half2_rn(x, y);
    return *(unsigned*)&h;
}
__device__ __forceinline__ float silu_f(float v) { return v * (1.0f/(1.0f+__expf(-v))); }

__device__ __forceinline__ int act_off(int m, int k) {
    return m*512 + ((((k>>3) ^ (m&7)) << 4) + (k&7)*2);
}
__device__ __forceinline__ int b_off(int n, int kc) {
    return n*128 + ((((kc>>3) ^ (n&7)) << 4) + (kc&7)*2);
}

// ---------------- edge stage (launch #1 for ncu visibility) ----------------
__device__ __forceinline__ void do_edge(
    int e, int is64, int c, const float* __restrict__ x,
    const float* __restrict__ rbf, const void* __restrict__ idx,
    const float* __restrict__ Wsh)
{
    const float2* rp2 = (const float2*)(rbf + (size_t)e * NRAD);
    float2 p0 = __ldcs(rp2), p1 = __ldcs(rp2 + 1), p2 = __ldcs(rp2 + 2);
    long long node = is64 ? __ldcs((const long long*)idx + e)
                          : (long long)__ldcs((const int*)idx + e);
    float4 xv = __ldcs((const float4*)(x + (size_t)e*HID + c));
    const float* W0 = Wsh + c;
    float w0 = p0.x*W0[0]+p0.y*W0[HID]+p1.x*W0[2*HID]+p1.y*W0[3*HID]+p2.x*W0[4*HID]+p2.y*W0[5*HID];
    float w1 = p0.x*W0[1]+p0.y*W0[HID+1]+p1.x*W0[2*HID+1]+p1.y*W0[3*HID+1]+p2.x*W0[4*HID+1]+p2.y*W0[5*HID+1];
    float w2 = p0.x*W0[2]+p0.y*W0[HID+2]+p1.x*W0[2*HID+2]+p1.y*W0[3*HID+2]+p2.x*W0[4*HID+2]+p2.y*W0[5*HID+2];
    float w3 = p0.x*W0[3]+p0.y*W0[HID+3]+p1.x*W0[2*HID+3]+p1.y*W0[3*HID+3]+p2.x*W0[4*HID+3]+p2.y*W0[5*HID+3];
    float* dst = g_hacc + (size_t)node*HID + c;
    asm volatile("red.global.add.v4.f32 [%0], {%1,%2,%3,%4};"
                 :: "l"(dst), "f"(w0*xv.x), "f"(w1*xv.y), "f"(w2*xv.z), "f"(w3*xv.w) : "memory");
}

__global__ void __launch_bounds__(256) edge_kernel(
    const float* __restrict__ x, const float* __restrict__ rbf,
    const void* __restrict__ idx, const float* __restrict__ Wr)
{
    __shared__ float Wsh[NRAD * HID];
    __shared__ int s64;
    if (threadIdx.x == 0) {
        int a = 1; const int* p = (const int*)idx;
        for (int k = 1; k < 64; k += 2) a &= (p[k] == 0);
        s64 = a;
    }
    for (int t = threadIdx.x; t < NRAD*HID; t += blockDim.x) Wsh[t] = Wr[t];
    __syncthreads();
    const int is64 = s64;
    const int c = (threadIdx.x & 31) * 4;
    const int warp = blockIdx.x*(blockDim.x>>5) + (threadIdx.x>>5);
    const int nwarp = gridDim.x*(blockDim.x>>5);
    for (int e = warp; e < E_NUM; e += 2*nwarp) {
        do_edge(e, is64, c, x, rbf, idx, Wsh);
        int e2 = e + nwarp;
        if (e2 < E_NUM) do_edge(e2, is64, c, x, rbf, idx, Wsh);
    }
}

// ---------------- prep: build fp16 W^T swizzled chunk images (no zeroing) ----
__global__ void __launch_bounds__(256) prep_kernel(const float* __restrict__ Wd,
                                                   const float* __restrict__ Ws)
{
    size_t stride = (size_t)gridDim.x * blockDim.x;
    for (size_t e = (size_t)blockIdx.x*blockDim.x + threadIdx.x; e < 229376; e += stride) {
        int l, k, n;
        if (e < 32768) { l = 0; k = (int)(e >> 8); n = (int)(e & 255); }
        else { size_t r = e - 32768; l = 1 + (int)(r >> 16); k = (int)((r >> 8) & 255); n = (int)(r & 255); }
        float w = (l == 0) ? Wd[k*256+n] : Ws[(size_t)(l-1)*65536 + k*256 + n];
        int chunk = k >> 6, kc = k & 63;
        int tile = (l == 0) ? chunk : 2 + (l-1)*4 + chunk;
        int dst = n*64 + (((kc>>3) ^ (n&7)) << 3) + (kc&7);
        g_wimg[(size_t)tile*16384 + dst] = __float2half_rn(w);
    }
}

// ---------------- MLP on mma.sync fp16; re-zeroes hacc after staging ----------
#define SMEM_DYN (32768 + 2*32768)

__global__ void __launch_bounds__(256, 2) mlp_kernel(const float* __restrict__ bs,
                                                     float* __restrict__ out)
{
    extern __shared__ char dsm[];
    char* act = dsm;                 // 32KB: 64 x 256 fp16 swizzled
    char* bbuf[2] = { dsm + 32768, dsm + 65536 };

    const int tid  = threadIdx.x;
    const int wid  = tid >> 5, lane = tid & 31;
    const int wm   = wid >> 2;
    const int wn   = wid & 3;
    const int gr   = lane >> 2;
    const int gc   = lane & 3;
    const int nodeBase = blockIdx.x * 64;

    // ---- stage layer-0 A (and re-zero consumed hacc rows for the next call)
    {
        int row = tid >> 2;
        int q   = tid & 3;
        int node = nodeBase + row;
        bool ok  = (node < NNODES);
        float4* src = (float4*)(g_hacc + (size_t)node * HID);
        const float4 z4 = make_float4(0.f,0.f,0.f,0.f);
#pragma unroll
        for (int w4 = 0; w4 < 8; w4++) {
            int k0 = q*32 + w4*4;
            float4 v = ok ? src[k0 >> 2] : z4;
            *(unsigned*)(act + act_off(row, k0))     = packh2(v.x, v.y);
            *(unsigned*)(act + act_off(row, k0 + 2)) = packh2(v.z, v.w);
            if (ok) src[k0 >> 2] = z4;
        }
    }
    __syncthreads();

    for (int l = 0; l < 4; l++) {
        const int nch   = (l == 0) ? 2 : 4;
        const int tbase = (l == 0) ? 0 : 2 + (l-1)*4;

        float C[2][8][4];
#pragma unroll
        for (int i=0;i<2;i++)
#pragma unroll
            for (int j=0;j<8;j++) { C[i][j][0]=0.f; C[i][j][1]=0.f; C[i][j][2]=0.f; C[i][j][3]=0.f; }

        {
            const char* src = (const char*)(g_wimg + (size_t)tbase*16384) + tid*16;
#pragma unroll
            for (int q = 0; q < 8; q++) cpa16(bbuf[0] + tid*16 + q*4096, src + q*4096);
            CP_COMMIT();
        }

        for (int c = 0; c < nch; c++) {
            const int b = c & 1;
            if (c + 1 < nch) {
                const char* src = (const char*)(g_wimg + (size_t)(tbase+c+1)*16384) + tid*16;
#pragma unroll
                for (int q = 0; q < 8; q++) cpa16(bbuf[b^1] + tid*16 + q*4096, src + q*4096);
                CP_COMMIT();
                CP_WAIT1();
            } else CP_WAIT0();
            __syncthreads();

            const char* bb = bbuf[b];
#pragma unroll
            for (int kk = 0; kk < 4; kk++) {
                const int kb = c*64 + kk*16;
                const int kc = kk*16;
                unsigned a[2][4];
#pragma unroll
                for (int i = 0; i < 2; i++) {
                    int m = wm*32 + i*16 + gr;
                    a[i][0] = *(const unsigned*)(act + act_off(m,     kb     + gc*2));
                    a[i][1] = *(const unsigned*)(act + act_off(m + 8, kb     + gc*2));
                    a[i][2] = *(const unsigned*)(act + act_off(m,     kb + 8 + gc*2));
                    a[i][3] = *(const unsigned*)(act + act_off(m + 8, kb + 8 + gc*2));
                }
#pragma unroll
                for (int j = 0; j < 8; j++) {
                    int n = wn*64 + j*8 + gr;
                    unsigned b0 = *(const unsigned*)(bb + b_off(n, kc     + gc*2));
                    unsigned b1 = *(const unsigned*)(bb + b_off(n, kc + 8 + gc*2));
#pragma unroll
                    for (int i = 0; i < 2; i++) mma16816(C[i][j], a[i], b0, b1);
                }
            }
            __syncthreads();
        }

        if (l < 3) {
#pragma unroll
            for (int i = 0; i < 2; i++) {
                int r0 = wm*32 + i*16 + gr;
#pragma unroll
                for (int j = 0; j < 8; j++) {
                    int n0 = wn*64 + j*8 + gc*2;
                    float v00=C[i][j][0], v01=C[i][j][1], v10=C[i][j][2], v11=C[i][j][3];
                    if (l > 0) {
                        float b0 = __ldg(bs + (l-1)*256 + n0), b1 = __ldg(bs + (l-1)*256 + n0 + 1);
                        v00 = silu_f(v00 + b0); v01 = silu_f(v01 + b1);
                        v10 = silu_f(v10 + b0); v11 = silu_f(v11 + b1);
                    }
                    *(unsigned*)(act + act_off(r0,     n0)) = packh2(v00, v01);
                    *(unsigned*)(act + act_off(r0 + 8, n0)) = packh2(v10, v11);
                }
            }
            __syncthreads();
        } else {
#pragma unroll
            for (int i = 0; i < 2; i++) {
                int r0 = wm*32 + i*16 + gr;
                long long node0 = nodeBase + r0, node1 = node0 + 8;
#pragma unroll
                for (int j = 0; j < 8; j++) {
                    int n0 = wn*64 + j*8 + gc*2;
                    float b0 = __ldg(bs + 512 + n0), b1 = __ldg(bs + 512 + n0 + 1);
                    if (node0 < NNODES) {
                        float* op = out + (size_t)node0*256 + n0;
                        op[0] = silu_f(C[i][j][0] + b0);
                        op[1] = silu_f(C[i][j][1] + b1);
                    }
                    if (node1 < NNODES) {
                        float* op = out + (size_t)node1*256 + n0;
                        op[0] = silu_f(C[i][j][2] + b0);
                        op[1] = silu_f(C[i][j][3] + b1);
                    }
                }
            }
        }
    }
}

// ---------------------------------------------------------------------------
extern "C" void kernel_launch(void* const* d_in, const int* in_sizes, int n_in,
                              void* d_out, int out_size)
{
    const float* x      = (const float*)d_in[0];
    const float* rbf    = (const float*)d_in[1];
    const void*  idx    = d_in[2];
    const float* W_rbf  = (const float*)d_in[3];
    const float* W_down = (const float*)d_in[4];
    const float* Ws     = (const float*)d_in[5];
    const float* bs     = (const float*)d_in[6];
    float* out = (float*)d_out;

    edge_kernel<<<1184, 256>>>(x, rbf, idx, W_rbf);
    prep_kernel<<<224, 256>>>(W_down, Ws);
    cudaFuncSetAttribute(mlp_kernel, cudaFuncAttributeMaxDynamicSharedMemorySize, SMEM_DYN);
    mlp_kernel<<<NT, 256, SMEM_DYN>>>(bs, out);
}